// round 7
// baseline (speedup 1.0000x reference)
#include <cuda_runtime.h>
#include <cuda_bf16.h>
#include <float.h>

// Problem constants
#define B_  16
#define Q_  300
#define T_  50
#define NC_ 80
#define H_  128
#define W_  128
#define NT_ (B_*T_)          // 800 targets
#define NHM (B_*NC_*H_*W_)   // 20,971,520 heatmap elements
#define N4_ (NHM/4)          // 5,242,880 float4

// One exact wave: 148 SMs * 6 blocks = 888 blocks, 256 threads (48 warps/SM).
#define NPREP  25            // 25 blocks * 32 k each = 800 targets
#define NCE    150           // 150 blocks * 8 warps * 4 rows = 4800 rows
#define NBLK   888
#define NFOCAL (NBLK - NPREP - NCE)            // 713
#define CHUNK  ((N4_ + NFOCAL - 1) / NFOCAL)   // 7354 float4 per focal block

// ---------------- device scratch (plain stores, no same-address atomics) ----------------
__device__ float    g_focal_part[NFOCAL];
__device__ float    g_ce_num_part[NCE];
__device__ float    g_ce_den_part[NCE];
__device__ float    g_prep_part[NPREP][5];   // bbox, giou, hm_corr, box_loss, num_pos
__device__ unsigned g_done = 0;

// ---------------- math helpers ----------------
// Exact-ish versions (used only on ~800 sparse elements in prep)
__device__ __forceinline__ float focal0(float x) {
    float e   = __expf(-fabsf(x));
    float sp  = fmaxf(x, 0.0f) + __logf(1.0f + e);
    float inv = __fdividef(1.0f, 1.0f + e);
    float p   = (x >= 0.0f) ? inv : (e * inv);
    return 0.75f * sp * p * p;
}
__device__ __forceinline__ float focal1(float x) {
    float e   = __expf(-fabsf(x));
    float sp  = fmaxf(-x, 0.0f) + __logf(1.0f + e);
    float inv = __fdividef(1.0f, 1.0f + e);
    float q   = (x >= 0.0f) ? (e * inv) : inv;
    return 0.25f * sp * q * q;
}

// Bulk focal (target=0), WITHOUT alpha: softplus(x)*sigmoid(x)^2.
// ONE MUFU (EX2). log1p(e) and 1/(1+e) via deg-6 polynomials in y=2e-1
// (truncated Chebyshev on e in [0,1]; abs err ~2e-6 / ~8e-6).
__device__ __forceinline__ float focal0_poly(float x) {
    float e  = __expf(-fabsf(x));            // FMUL + MUFU.EX2, e in (0,1]
    float y  = fmaf(2.0f, e, -1.0f);         // y in (-1,1]
    float y2 = y*y;
    float y3 = y2*y;
    float y4 = y2*y2;
    float y5 = y2*y3;
    float y6 = y3*y3;
    // L ~= log1p(e)
    float L = fmaf(0.33334270f, y,  0.40546551f);
    L = fmaf(-0.05556130f, y2, L);
    L = fmaf( 0.01227780f, y3, L);
    L = fmaf(-0.00305814f, y4, L);
    L = fmaf( 0.00095152f, y5, L);
    L = fmaf(-0.00027206f, y6, L);
    // r ~= 1/(1+e)
    float r = fmaf(-0.22226589f, y,  0.66666564f);
    r = fmaf( 0.07410646f, y2, r);
    r = fmaf(-0.02436280f, y3, r);
    r = fmaf( 0.00807256f, y4, r);
    r = fmaf(-0.00336432f, y5, r);
    r = fmaf( 0.00115424f, y6, r);
    float sp = fmaxf(x, 0.0f) + L;           // softplus(x)
    float q  = (x >= 0.0f) ? r : e * r;      // sigmoid(x)
    return sp * q * q;
}
__device__ __forceinline__ float focal4(const float4 v) {
    return focal0_poly(v.x) + focal0_poly(v.y) + focal0_poly(v.z) + focal0_poly(v.w);
}

__global__ void __launch_bounds__(256, 6)
fused_kernel(const float*  __restrict__ pred_logits,
             const float*  __restrict__ pred_boxes,
             const float4* __restrict__ heatmap4,
             const float*  __restrict__ box_map,
             const float*  __restrict__ tgt_boxes,
             const int*    __restrict__ tgt_labels,
             const float*  __restrict__ tgt_sizes,
             const int*    __restrict__ src_idx,
             const int*    __restrict__ tgt_idx,
             const float*  __restrict__ ew,
             float*        __restrict__ out)
{
    const int tid  = threadIdx.x;
    const int lane = tid & 31;
    const int wid  = tid >> 5;
    const int bx   = blockIdx.x;
    const float* heatmap = (const float*)heatmap4;

    __shared__ int    s_pk[NT_];       // packed key: (b<<21)|(gy<<14)|(gx<<7)|lab
    __shared__ float  s_bf[NT_*4];     // normalized cxcywh
    __shared__ float  s_red[8*5];
    __shared__ double s_dred[8*3];
    __shared__ bool   s_last;

    if (bx >= NPREP + NCE) {
        // ===== FOCAL: bulk poly-focal over a contiguous chunk, double-buffered =====
        const int fid   = bx - NPREP - NCE;
        const int start = fid * CHUNK;
        const int end   = min(start + CHUNK, N4_);
        float acc = 0.f;

        int i = start + tid;
        float4 c0, c1;
        bool have = (i + 256 < end);
        if (have) { c0 = heatmap4[i]; c1 = heatmap4[i + 256]; }
        while (have) {
            const int j = i + 512;
            const bool nxt = (j + 256 < end);
            float4 t0, t1;
            if (nxt) { t0 = heatmap4[j]; t1 = heatmap4[j + 256]; }  // prefetch next pair
            acc += focal4(c0);
            acc += focal4(c1);
            c0 = t0; c1 = t1;
            i = j; have = nxt;
        }
        for (; i < end; i += 256) {
            acc += focal4(heatmap4[i]);
        }
        acc *= 0.75f;    // alpha factor once per thread
        #pragma unroll
        for (int o = 16; o; o >>= 1) acc += __shfl_xor_sync(0xffffffffu, acc, o);
        if (lane == 0) s_red[wid*5] = acc;
        __syncthreads();
        if (tid == 0) {
            float r = 0.f;
            #pragma unroll
            for (int j = 0; j < 8; j++) r += s_red[j*5];
            g_focal_part[fid] = r;
        }
    }
    else if (bx >= NPREP) {
        // ================= CE: weighted log-softmax over 81 classes =================
        const int cid = bx - NPREP;
        float l_num = 0.f, l_den = 0.f;
        #pragma unroll
        for (int rr = 0; rr < 4; rr++) {
            int r = cid*32 + wid*4 + rr;          // row in [0, 4800)
            int b = r / Q_;
            int q = r - b*Q_;
            // find matched target slot: src_idx[b][t] == q (entries distinct per b)
            int cand = -1;
            int s1 = (lane < T_) ? src_idx[b*T_ + lane] : -1;
            if (s1 == q) cand = lane;
            int t2 = lane + 32;
            if (t2 < T_) {
                int s2 = src_idx[b*T_ + t2];
                if (s2 == q) cand = t2;
            }
            #pragma unroll
            for (int o = 16; o; o >>= 1) cand = max(cand, __shfl_xor_sync(0xffffffffu, cand, o));
            int tc = NC_;
            if (cand >= 0) tc = tgt_labels[b*T_ + tgt_idx[b*T_ + cand]];

            const float* row = &pred_logits[r * (NC_+1)];
            float v0 = row[lane];
            float v1 = row[lane + 32];
            float v2 = (lane < 17) ? row[lane + 64] : -FLT_MAX;
            float m = fmaxf(fmaxf(v0, v1), v2);
            #pragma unroll
            for (int o = 16; o; o >>= 1) m = fmaxf(m, __shfl_xor_sync(0xffffffffu, m, o));
            float s = __expf(v0 - m) + __expf(v1 - m) + ((lane < 17) ? __expf(v2 - m) : 0.0f);
            #pragma unroll
            for (int o = 16; o; o >>= 1) s += __shfl_xor_sync(0xffffffffu, s, o);
            if (lane == 0) {
                float nll = __logf(s) + m - row[tc];
                float cw  = ew[tc];
                l_num += cw * nll;
                l_den += cw;
            }
        }
        if (lane == 0) { s_red[wid*5+0] = l_num; s_red[wid*5+1] = l_den; }
        __syncthreads();
        if (tid == 0) {
            float rn=0, rd=0;
            #pragma unroll
            for (int i = 0; i < 8; i++) { rn += s_red[i*5+0]; rd += s_red[i*5+1]; }
            g_ce_num_part[cid] = rn;
            g_ce_den_part[cid] = rd;
        }
    }
    else {
        // ================= PREP =================
        const int bp = bx;
        // Phase A: all 800 packed keys + normalized boxes (every prep block recomputes)
        for (int k = tid; k < NT_; k += 256) {
            int b = k / T_;
            float h_im = tgt_sizes[b*2 + 0];
            float w_im = tgt_sizes[b*2 + 1];
            float x1 = tgt_boxes[k*4+0] / w_im;
            float y1 = tgt_boxes[k*4+1] / h_im;
            float x2 = tgt_boxes[k*4+2] / w_im;
            float y2 = tgt_boxes[k*4+3] / h_im;
            float cx = 0.5f*(x1+x2), cy = 0.5f*(y1+y2);
            float w  = x2-x1,        h  = y2-y1;
            s_bf[k*4+0]=cx; s_bf[k*4+1]=cy; s_bf[k*4+2]=w; s_bf[k*4+3]=h;
            int gx = min(max((int)(cx * (float)W_), 0), W_-1);
            int gy = min(max((int)(cy * (float)H_), 0), H_-1);
            int lab = tgt_labels[k];
            s_pk[k] = (b << 21) | (gy << 14) | (gx << 7) | lab;
        }
        __syncthreads();

        float l_bbox = 0.f, l_giou = 0.f, l_hm = 0.f, l_box = 0.f, l_np = 0.f;

        // Phase B: matched pairs (this block's 32 targets) -> bbox L1 + GIoU
        if (tid < 32) {
            int k = bp*32 + tid;
            int b = k / T_;
            int s = src_idx[k];
            int j = tgt_idx[k];
            const float* sb = &pred_boxes[(b*Q_ + s)*4];
            const float* tb = &s_bf[(b*T_ + j)*4];
            float scx=sb[0], scy=sb[1], sw=sb[2], sh=sb[3];
            float tcx=tb[0], tcy=tb[1], tw=tb[2], th=tb[3];

            l_bbox = fabsf(scx-tcx)+fabsf(scy-tcy)+fabsf(sw-tw)+fabsf(sh-th);

            float ax1=scx-0.5f*sw, ay1=scy-0.5f*sh, ax2=scx+0.5f*sw, ay2=scy+0.5f*sh;
            float bx1=tcx-0.5f*tw, by1=tcy-0.5f*th, bx2=tcx+0.5f*tw, by2=tcy+0.5f*th;
            float area_a = (ax2-ax1)*(ay2-ay1);
            float area_b = (bx2-bx1)*(by2-by1);
            float iw = fmaxf(fminf(ax2,bx2)-fmaxf(ax1,bx1), 0.0f);
            float ih = fmaxf(fminf(ay2,by2)-fmaxf(ay1,by1), 0.0f);
            float inter = iw*ih;
            float uni   = area_a + area_b - inter;
            float iou   = inter / uni;
            float cw = fmaxf(fmaxf(ax2,bx2)-fminf(ax1,bx1), 0.0f);
            float ch = fmaxf(fmaxf(ay2,by2)-fminf(ay1,by1), 0.0f);
            float area_c = cw*ch;
            float giou = iou - (area_c - uni)/area_c;
            l_giou = 1.0f - giou;
        }

        // Phase C: branch-free dedupe, 8 threads per target k, 100 m's each
        {
            const int k   = bp*32 + (tid >> 3);      // this block's target
            const int sub = tid & 7;
            const int mypk = s_pk[k];
            int winner  = k;
            int pos_hit = 0, hm_hit = 0;
            const int m0 = sub * 100;
            #pragma unroll 4
            for (int m = m0; m < m0 + 100; m++) {
                int pk = s_pk[m];
                int sc = ((pk ^ mypk) & ~127) == 0;     // same (b,gy,gx)
                pos_hit |= sc & (m < k);
                hm_hit  |= (pk == mypk) & (m < k);
                winner = (sc && m > winner) ? m : winner;
            }
            // width-8 subgroup reduction
            #pragma unroll
            for (int o = 4; o; o >>= 1) {
                pos_hit |= __shfl_xor_sync(0xffffffffu, pos_hit, o);
                hm_hit  |= __shfl_xor_sync(0xffffffffu, hm_hit,  o);
                winner   = max(winner, __shfl_xor_sync(0xffffffffu, winner, o));
            }
            if (sub == 0) {
                int lab = mypk & 127;
                int gx  = (mypk >> 7)  & 127;
                int gy  = (mypk >> 14) & 127;
                int b   = mypk >> 21;
                if (!hm_hit) {   // first (b,cell,lab) occurrence -> heatmap correction
                    float x = heatmap[(((b*NC_ + lab)*H_) + gy)*W_ + gx];
                    l_hm = focal1(x) - focal0(x);
                }
                if (!pos_hit) {  // first (b,cell) occurrence -> counts + box loss
                    l_np = 1.0f;
                    const float* wf = &s_bf[winner*4];
                    #pragma unroll
                    for (int c = 0; c < 4; c++) {
                        float v = box_map[(((b*4 + c)*H_) + gy)*W_ + gx];
                        l_box += fabsf(v - wf[c]);
                    }
                }
            }
        }

        // block reduce 5 floats
        #pragma unroll
        for (int o = 16; o; o >>= 1) {
            l_bbox += __shfl_xor_sync(0xffffffffu, l_bbox, o);
            l_giou += __shfl_xor_sync(0xffffffffu, l_giou, o);
            l_hm   += __shfl_xor_sync(0xffffffffu, l_hm,   o);
            l_box  += __shfl_xor_sync(0xffffffffu, l_box,  o);
            l_np   += __shfl_xor_sync(0xffffffffu, l_np,   o);
        }
        if (lane == 0) {
            s_red[wid*5+0]=l_bbox; s_red[wid*5+1]=l_giou; s_red[wid*5+2]=l_hm;
            s_red[wid*5+3]=l_box;  s_red[wid*5+4]=l_np;
        }
        __syncthreads();
        if (tid < 5) {
            float r = 0.f;
            #pragma unroll
            for (int i = 0; i < 8; i++) r += s_red[i*5+tid];
            g_prep_part[bp][tid] = r;
        }
    }

    // ================= completion protocol: last block finalizes =================
    __syncthreads();
    __threadfence();
    if (tid == 0) {
        unsigned t = atomicAdd(&g_done, 1u);
        s_last = (t == NBLK - 1);
    }
    __syncthreads();
    if (!s_last) return;

    // parallel sum of all partials in double
    double fsum = 0.0, cnum = 0.0, cden = 0.0;
    for (int i = tid; i < NFOCAL; i += 256) fsum += (double)g_focal_part[i];
    for (int i = tid; i < NCE;    i += 256) {
        cnum += (double)g_ce_num_part[i];
        cden += (double)g_ce_den_part[i];
    }
    double pb = 0.0, pg = 0.0, ph = 0.0, px = 0.0, pn = 0.0;
    if (tid < NPREP) {
        pb = (double)g_prep_part[tid][0];
        pg = (double)g_prep_part[tid][1];
        ph = (double)g_prep_part[tid][2];
        px = (double)g_prep_part[tid][3];
        pn = (double)g_prep_part[tid][4];
    }
    fsum += ph;      // fold hm correction into focal sum
    #pragma unroll
    for (int o = 16; o; o >>= 1) {
        fsum += __shfl_xor_sync(0xffffffffu, fsum, o);
        cnum += __shfl_xor_sync(0xffffffffu, cnum, o);
        cden += __shfl_xor_sync(0xffffffffu, cden, o);
        pb   += __shfl_xor_sync(0xffffffffu, pb,   o);
        pg   += __shfl_xor_sync(0xffffffffu, pg,   o);
        px   += __shfl_xor_sync(0xffffffffu, px,   o);
        pn   += __shfl_xor_sync(0xffffffffu, pn,   o);
    }
    if (lane == 0) {
        s_dred[wid]    = fsum;
        s_dred[8+wid]  = cnum;
        s_dred[16+wid] = cden;
        s_red[wid*5+0] = (float)pb;
        s_red[wid*5+1] = (float)pg;
        s_red[wid*5+2] = (float)px;
        s_red[wid*5+3] = (float)pn;
    }
    __syncthreads();
    if (tid == 0) {
        double F=0, CN=0, CD=0, Pb=0, Pg=0, Px=0, Pn=0;
        #pragma unroll
        for (int i = 0; i < 8; i++) {
            F  += s_dred[i]; CN += s_dred[8+i]; CD += s_dred[16+i];
            Pb += (double)s_red[i*5+0]; Pg += (double)s_red[i*5+1];
            Px += (double)s_red[i*5+2]; Pn += (double)s_red[i*5+3];
        }
        double num_boxes = (double)(B_*T_);
        double num_pos   = fmax(Pn, 1.0);
        double ce   = CN / CD;
        double bbox = Pb / num_boxes;
        double giou = Pg / num_boxes;
        double hm   = F  / num_pos;
        double bxl  = Px / num_pos;
        double aux  = 1.0*hm + 5.0*bxl;                 // AUX_HM_W, AUX_BOX_W
        double tot  = 1.0*ce + 5.0*bbox + 2.0*giou + 1.0*aux;
        out[0] = (float)ce;
        out[1] = (float)bbox;
        out[2] = (float)giou;
        out[3] = (float)aux;
        out[4] = (float)tot;
        g_done = 0;   // reset for next graph replay
    }
}

// ---------------- launch ----------------
extern "C" void kernel_launch(void* const* d_in, const int* in_sizes, int n_in,
                              void* d_out, int out_size)
{
    const float* pred_logits   = (const float*)d_in[0];
    const float* pred_boxes    = (const float*)d_in[1];
    const float* heatmap       = (const float*)d_in[2];
    const float* box_map       = (const float*)d_in[3];
    const float* tgt_boxes     = (const float*)d_in[4];
    const int*   tgt_labels    = (const int*)  d_in[5];
    const float* tgt_sizes     = (const float*)d_in[6];
    const int*   src_idx       = (const int*)  d_in[7];
    const int*   tgt_idx       = (const int*)  d_in[8];
    const float* empty_weight  = (const float*)d_in[9];
    float* out = (float*)d_out;

    fused_kernel<<<NBLK, 256>>>(pred_logits, pred_boxes, (const float4*)heatmap,
                                box_map, tgt_boxes, tgt_labels, tgt_sizes,
                                src_idx, tgt_idx, empty_weight, out);
}

// round 8
// speedup vs baseline: 1.1979x; 1.1979x over previous
#include <cuda_runtime.h>
#include <cuda_bf16.h>
#include <float.h>

// Problem constants
#define B_  16
#define Q_  300
#define T_  50
#define NC_ 80
#define H_  128
#define W_  128
#define NT_ (B_*T_)          // 800 targets
#define NHM (B_*NC_*H_*W_)   // 20,971,520 heatmap elements
#define N4_ (NHM/4)          // 5,242,880 float4

// One exact wave: 148 SMs * 8 blocks = 1184 blocks, 256 threads (64 warps/SM).
#define NPREP  25            // 25 blocks * 32 k each = 800 targets
#define NCE    150           // 150 blocks * 8 warps * 4 rows = 4800 rows
#define NBLK   1184
#define NFOCAL (NBLK - NPREP - NCE)            // 1009
#define CHUNK  ((N4_ + NFOCAL - 1) / NFOCAL)   // 5197 float4 per focal block

// ---------------- device scratch (plain stores, no same-address atomics) ----------------
__device__ float    g_focal_part[NFOCAL];
__device__ float    g_ce_num_part[NCE];
__device__ float    g_ce_den_part[NCE];
__device__ float    g_prep_part[NPREP][5];   // bbox, giou, hm_corr, box_loss, num_pos
__device__ unsigned g_done = 0;

// ---------------- math helpers ----------------
// Exact versions (used only on ~800 sparse elements in prep)
__device__ __forceinline__ float focal0(float x) {
    float e   = __expf(-fabsf(x));
    float sp  = fmaxf(x, 0.0f) + __logf(1.0f + e);
    float inv = __fdividef(1.0f, 1.0f + e);
    float p   = (x >= 0.0f) ? inv : (e * inv);
    return 0.75f * sp * p * p;
}
__device__ __forceinline__ float focal1(float x) {
    float e   = __expf(-fabsf(x));
    float sp  = fmaxf(-x, 0.0f) + __logf(1.0f + e);
    float inv = __fdividef(1.0f, 1.0f + e);
    float q   = (x >= 0.0f) ? (e * inv) : inv;
    return 0.25f * sp * q * q;
}

// Bulk focal (target=0), WITHOUT alpha: softplus(x)*sigmoid(x)^2.
// Branch-free, minimal-issue form. Valid while exp(-x) stays finite
// (|x| << 88; heatmap logits are ~N(0,1)).
//   e = exp(-x); u = 1+e; f = (x + log u) * (1/u)^2
// 10 issues/element: FMUL+EX2, FADD, LG2+FMUL, RCP, FADD(x+L), FMUL, FMUL, FADD(acc)
__device__ __forceinline__ float focal0_fast(float x) {
    float e  = __expf(-x);
    float u  = 1.0f + e;
    float L  = __logf(u);
    float r  = __fdividef(1.0f, u);
    return (x + L) * r * r;
}
__device__ __forceinline__ float focal4(const float4 v) {
    return focal0_fast(v.x) + focal0_fast(v.y) + focal0_fast(v.z) + focal0_fast(v.w);
}

__global__ void __launch_bounds__(256, 8)
fused_kernel(const float*  __restrict__ pred_logits,
             const float*  __restrict__ pred_boxes,
             const float4* __restrict__ heatmap4,
             const float*  __restrict__ box_map,
             const float*  __restrict__ tgt_boxes,
             const int*    __restrict__ tgt_labels,
             const float*  __restrict__ tgt_sizes,
             const int*    __restrict__ src_idx,
             const int*    __restrict__ tgt_idx,
             const float*  __restrict__ ew,
             float*        __restrict__ out)
{
    const int tid  = threadIdx.x;
    const int lane = tid & 31;
    const int wid  = tid >> 5;
    const int bx   = blockIdx.x;
    const float* heatmap = (const float*)heatmap4;

    __shared__ int    s_pk[NT_];       // packed key: (b<<21)|(gy<<14)|(gx<<7)|lab
    __shared__ float  s_bf[NT_*4];     // normalized cxcywh
    __shared__ float  s_red[8*5];
    __shared__ double s_dred[8*3];
    __shared__ bool   s_last;

    if (bx >= NPREP + NCE) {
        // ===== FOCAL: bulk focal over a contiguous chunk, double-buffered =====
        const int fid   = bx - NPREP - NCE;
        const int start = fid * CHUNK;
        const int end   = min(start + CHUNK, N4_);
        float acc = 0.f;

        int i = start + tid;
        float4 c0, c1;
        bool have = (i + 256 < end);
        if (have) { c0 = heatmap4[i]; c1 = heatmap4[i + 256]; }
        while (have) {
            const int j = i + 512;
            const bool nxt = (j + 256 < end);
            float4 t0, t1;
            if (nxt) { t0 = heatmap4[j]; t1 = heatmap4[j + 256]; }  // prefetch next pair
            acc += focal4(c0);
            acc += focal4(c1);
            c0 = t0; c1 = t1;
            i = j; have = nxt;
        }
        for (; i < end; i += 256) {
            acc += focal4(heatmap4[i]);
        }
        acc *= 0.75f;    // alpha factor once per thread
        #pragma unroll
        for (int o = 16; o; o >>= 1) acc += __shfl_xor_sync(0xffffffffu, acc, o);
        if (lane == 0) s_red[wid*5] = acc;
        __syncthreads();
        if (tid == 0) {
            float r = 0.f;
            #pragma unroll
            for (int j = 0; j < 8; j++) r += s_red[j*5];
            g_focal_part[fid] = r;
        }
    }
    else if (bx >= NPREP) {
        // ================= CE: weighted log-softmax over 81 classes =================
        const int cid = bx - NPREP;
        float l_num = 0.f, l_den = 0.f;
        #pragma unroll
        for (int rr = 0; rr < 4; rr++) {
            int r = cid*32 + wid*4 + rr;          // row in [0, 4800)
            int b = r / Q_;
            int q = r - b*Q_;
            // find matched target slot: src_idx[b][t] == q (entries distinct per b)
            int cand = -1;
            int s1 = (lane < T_) ? src_idx[b*T_ + lane] : -1;
            if (s1 == q) cand = lane;
            int t2 = lane + 32;
            if (t2 < T_) {
                int s2 = src_idx[b*T_ + t2];
                if (s2 == q) cand = t2;
            }
            #pragma unroll
            for (int o = 16; o; o >>= 1) cand = max(cand, __shfl_xor_sync(0xffffffffu, cand, o));
            int tc = NC_;
            if (cand >= 0) tc = tgt_labels[b*T_ + tgt_idx[b*T_ + cand]];

            const float* row = &pred_logits[r * (NC_+1)];
            float v0 = row[lane];
            float v1 = row[lane + 32];
            float v2 = (lane < 17) ? row[lane + 64] : -FLT_MAX;
            float m = fmaxf(fmaxf(v0, v1), v2);
            #pragma unroll
            for (int o = 16; o; o >>= 1) m = fmaxf(m, __shfl_xor_sync(0xffffffffu, m, o));
            float s = __expf(v0 - m) + __expf(v1 - m) + ((lane < 17) ? __expf(v2 - m) : 0.0f);
            #pragma unroll
            for (int o = 16; o; o >>= 1) s += __shfl_xor_sync(0xffffffffu, s, o);
            if (lane == 0) {
                float nll = __logf(s) + m - row[tc];
                float cw  = ew[tc];
                l_num += cw * nll;
                l_den += cw;
            }
        }
        if (lane == 0) { s_red[wid*5+0] = l_num; s_red[wid*5+1] = l_den; }
        __syncthreads();
        if (tid == 0) {
            float rn=0, rd=0;
            #pragma unroll
            for (int i = 0; i < 8; i++) { rn += s_red[i*5+0]; rd += s_red[i*5+1]; }
            g_ce_num_part[cid] = rn;
            g_ce_den_part[cid] = rd;
        }
    }
    else {
        // ================= PREP =================
        const int bp = bx;
        // Phase A: all 800 packed keys + normalized boxes (every prep block recomputes)
        for (int k = tid; k < NT_; k += 256) {
            int b = k / T_;
            float h_im = tgt_sizes[b*2 + 0];
            float w_im = tgt_sizes[b*2 + 1];
            float x1 = tgt_boxes[k*4+0] / w_im;
            float y1 = tgt_boxes[k*4+1] / h_im;
            float x2 = tgt_boxes[k*4+2] / w_im;
            float y2 = tgt_boxes[k*4+3] / h_im;
            float cx = 0.5f*(x1+x2), cy = 0.5f*(y1+y2);
            float w  = x2-x1,        h  = y2-y1;
            s_bf[k*4+0]=cx; s_bf[k*4+1]=cy; s_bf[k*4+2]=w; s_bf[k*4+3]=h;
            int gx = min(max((int)(cx * (float)W_), 0), W_-1);
            int gy = min(max((int)(cy * (float)H_), 0), H_-1);
            int lab = tgt_labels[k];
            s_pk[k] = (b << 21) | (gy << 14) | (gx << 7) | lab;
        }
        __syncthreads();

        float l_bbox = 0.f, l_giou = 0.f, l_hm = 0.f, l_box = 0.f, l_np = 0.f;

        // Phase B: matched pairs (this block's 32 targets) -> bbox L1 + GIoU
        if (tid < 32) {
            int k = bp*32 + tid;
            int b = k / T_;
            int s = src_idx[k];
            int j = tgt_idx[k];
            const float* sb = &pred_boxes[(b*Q_ + s)*4];
            const float* tb = &s_bf[(b*T_ + j)*4];
            float scx=sb[0], scy=sb[1], sw=sb[2], sh=sb[3];
            float tcx=tb[0], tcy=tb[1], tw=tb[2], th=tb[3];

            l_bbox = fabsf(scx-tcx)+fabsf(scy-tcy)+fabsf(sw-tw)+fabsf(sh-th);

            float ax1=scx-0.5f*sw, ay1=scy-0.5f*sh, ax2=scx+0.5f*sw, ay2=scy+0.5f*sh;
            float bx1=tcx-0.5f*tw, by1=tcy-0.5f*th, bx2=tcx+0.5f*tw, by2=tcy+0.5f*th;
            float area_a = (ax2-ax1)*(ay2-ay1);
            float area_b = (bx2-bx1)*(by2-by1);
            float iw = fmaxf(fminf(ax2,bx2)-fmaxf(ax1,bx1), 0.0f);
            float ih = fmaxf(fminf(ay2,by2)-fmaxf(ay1,by1), 0.0f);
            float inter = iw*ih;
            float uni   = area_a + area_b - inter;
            float iou   = inter / uni;
            float cw = fmaxf(fmaxf(ax2,bx2)-fminf(ax1,bx1), 0.0f);
            float ch = fmaxf(fmaxf(ay2,by2)-fminf(ay1,by1), 0.0f);
            float area_c = cw*ch;
            float giou = iou - (area_c - uni)/area_c;
            l_giou = 1.0f - giou;
        }

        // Phase C: branch-free dedupe, 8 threads per target k, 100 m's each
        {
            const int k   = bp*32 + (tid >> 3);      // this block's target
            const int sub = tid & 7;
            const int mypk = s_pk[k];
            int winner  = k;
            int pos_hit = 0, hm_hit = 0;
            const int m0 = sub * 100;
            #pragma unroll 4
            for (int m = m0; m < m0 + 100; m++) {
                int pk = s_pk[m];
                int sc = ((pk ^ mypk) & ~127) == 0;     // same (b,gy,gx)
                pos_hit |= sc & (m < k);
                hm_hit  |= (pk == mypk) & (m < k);
                winner = (sc && m > winner) ? m : winner;
            }
            // width-8 subgroup reduction
            #pragma unroll
            for (int o = 4; o; o >>= 1) {
                pos_hit |= __shfl_xor_sync(0xffffffffu, pos_hit, o);
                hm_hit  |= __shfl_xor_sync(0xffffffffu, hm_hit,  o);
                winner   = max(winner, __shfl_xor_sync(0xffffffffu, winner, o));
            }
            if (sub == 0) {
                int lab = mypk & 127;
                int gx  = (mypk >> 7)  & 127;
                int gy  = (mypk >> 14) & 127;
                int b   = mypk >> 21;
                if (!hm_hit) {   // first (b,cell,lab) occurrence -> heatmap correction
                    float x = heatmap[(((b*NC_ + lab)*H_) + gy)*W_ + gx];
                    l_hm = focal1(x) - focal0(x);
                }
                if (!pos_hit) {  // first (b,cell) occurrence -> counts + box loss
                    l_np = 1.0f;
                    const float* wf = &s_bf[winner*4];
                    #pragma unroll
                    for (int c = 0; c < 4; c++) {
                        float v = box_map[(((b*4 + c)*H_) + gy)*W_ + gx];
                        l_box += fabsf(v - wf[c]);
                    }
                }
            }
        }

        // block reduce 5 floats
        #pragma unroll
        for (int o = 16; o; o >>= 1) {
            l_bbox += __shfl_xor_sync(0xffffffffu, l_bbox, o);
            l_giou += __shfl_xor_sync(0xffffffffu, l_giou, o);
            l_hm   += __shfl_xor_sync(0xffffffffu, l_hm,   o);
            l_box  += __shfl_xor_sync(0xffffffffu, l_box,  o);
            l_np   += __shfl_xor_sync(0xffffffffu, l_np,   o);
        }
        if (lane == 0) {
            s_red[wid*5+0]=l_bbox; s_red[wid*5+1]=l_giou; s_red[wid*5+2]=l_hm;
            s_red[wid*5+3]=l_box;  s_red[wid*5+4]=l_np;
        }
        __syncthreads();
        if (tid < 5) {
            float r = 0.f;
            #pragma unroll
            for (int i = 0; i < 8; i++) r += s_red[i*5+tid];
            g_prep_part[bp][tid] = r;
        }
    }

    // ================= completion protocol: last block finalizes =================
    __syncthreads();
    __threadfence();
    if (tid == 0) {
        unsigned t = atomicAdd(&g_done, 1u);
        s_last = (t == NBLK - 1);
    }
    __syncthreads();
    if (!s_last) return;

    // parallel sum of all partials in double
    double fsum = 0.0, cnum = 0.0, cden = 0.0;
    for (int i = tid; i < NFOCAL; i += 256) fsum += (double)g_focal_part[i];
    for (int i = tid; i < NCE;    i += 256) {
        cnum += (double)g_ce_num_part[i];
        cden += (double)g_ce_den_part[i];
    }
    double pb = 0.0, pg = 0.0, ph = 0.0, px = 0.0, pn = 0.0;
    if (tid < NPREP) {
        pb = (double)g_prep_part[tid][0];
        pg = (double)g_prep_part[tid][1];
        ph = (double)g_prep_part[tid][2];
        px = (double)g_prep_part[tid][3];
        pn = (double)g_prep_part[tid][4];
    }
    fsum += ph;      // fold hm correction into focal sum
    #pragma unroll
    for (int o = 16; o; o >>= 1) {
        fsum += __shfl_xor_sync(0xffffffffu, fsum, o);
        cnum += __shfl_xor_sync(0xffffffffu, cnum, o);
        cden += __shfl_xor_sync(0xffffffffu, cden, o);
        pb   += __shfl_xor_sync(0xffffffffu, pb,   o);
        pg   += __shfl_xor_sync(0xffffffffu, pg,   o);
        px   += __shfl_xor_sync(0xffffffffu, px,   o);
        pn   += __shfl_xor_sync(0xffffffffu, pn,   o);
    }
    if (lane == 0) {
        s_dred[wid]    = fsum;
        s_dred[8+wid]  = cnum;
        s_dred[16+wid] = cden;
        s_red[wid*5+0] = (float)pb;
        s_red[wid*5+1] = (float)pg;
        s_red[wid*5+2] = (float)px;
        s_red[wid*5+3] = (float)pn;
    }
    __syncthreads();
    if (tid == 0) {
        double F=0, CN=0, CD=0, Pb=0, Pg=0, Px=0, Pn=0;
        #pragma unroll
        for (int i = 0; i < 8; i++) {
            F  += s_dred[i]; CN += s_dred[8+i]; CD += s_dred[16+i];
            Pb += (double)s_red[i*5+0]; Pg += (double)s_red[i*5+1];
            Px += (double)s_red[i*5+2]; Pn += (double)s_red[i*5+3];
        }
        double num_boxes = (double)(B_*T_);
        double num_pos   = fmax(Pn, 1.0);
        double ce   = CN / CD;
        double bbox = Pb / num_boxes;
        double giou = Pg / num_boxes;
        double hm   = F  / num_pos;
        double bxl  = Px / num_pos;
        double aux  = 1.0*hm + 5.0*bxl;                 // AUX_HM_W, AUX_BOX_W
        double tot  = 1.0*ce + 5.0*bbox + 2.0*giou + 1.0*aux;
        out[0] = (float)ce;
        out[1] = (float)bbox;
        out[2] = (float)giou;
        out[3] = (float)aux;
        out[4] = (float)tot;
        g_done = 0;   // reset for next graph replay
    }
}

// ---------------- launch ----------------
extern "C" void kernel_launch(void* const* d_in, const int* in_sizes, int n_in,
                              void* d_out, int out_size)
{
    const float* pred_logits   = (const float*)d_in[0];
    const float* pred_boxes    = (const float*)d_in[1];
    const float* heatmap       = (const float*)d_in[2];
    const float* box_map       = (const float*)d_in[3];
    const float* tgt_boxes     = (const float*)d_in[4];
    const int*   tgt_labels    = (const int*)  d_in[5];
    const float* tgt_sizes     = (const float*)d_in[6];
    const int*   src_idx       = (const int*)  d_in[7];
    const int*   tgt_idx       = (const int*)  d_in[8];
    const float* empty_weight  = (const float*)d_in[9];
    float* out = (float*)d_out;

    fused_kernel<<<NBLK, 256>>>(pred_logits, pred_boxes, (const float4*)heatmap,
                                box_map, tgt_boxes, tgt_labels, tgt_sizes,
                                src_idx, tgt_idx, empty_weight, out);
}